// round 8
// baseline (speedup 1.0000x reference)
#include <cuda_runtime.h>

// Problem constants
#define Bn   2
#define Sn   2048
#define DMn  1024
#define DKn  64
#define Hn   16
#define Tn   (Bn * Sn)   // 4096 tokens

// Scratch (device globals; allocation-free per harness rules)
__device__ float g_q[(size_t)Bn * Hn * Sn * DKn];   // [B,H,S,64] 16MB
__device__ float g_k[(size_t)Bn * Hn * Sn * DKn];
__device__ float g_v[(size_t)Bn * Hn * Sn * DKn];
__device__ float g_ctx[(size_t)Tn * DMn];           // [B*S, 1024] 16MB

// ============================================================================
// Kernel 1: QKV projection. grid = (Tn/128, 48), block = 256.
// blockIdx.y -> (proj, head). C_tile[128 x 64] = x[128 x 1024] @ W_head[1024 x 64]
// ============================================================================
__global__ __launch_bounds__(256) void qkv_kernel(
    const float* __restrict__ x,
    const float* __restrict__ Wq,
    const float* __restrict__ Wk,
    const float* __restrict__ Wv)
{
    __shared__ float As[16][132];   // transposed x tile, padded (+4) for banks
    __shared__ float Bs[16][64];    // W tile

    const int pz   = blockIdx.y;
    const int proj = pz >> 4;
    const int head = pz & 15;
    const float* W = (proj == 0 ? Wq : (proj == 1 ? Wk : Wv)) + (size_t)head * DMn * DKn;
    float* out = (proj == 0 ? g_q : (proj == 1 ? g_k : g_v));

    const int row0 = blockIdx.x * 128;
    const int tid  = threadIdx.x;
    const int tx   = tid & 15;   // 16 col-groups of 4
    const int ty   = tid >> 4;   // 16 row-groups of 8

    float acc[8][4];
    #pragma unroll
    for (int i = 0; i < 8; i++) {
        acc[i][0] = 0.f; acc[i][1] = 0.f; acc[i][2] = 0.f; acc[i][3] = 0.f;
    }

    for (int k0 = 0; k0 < DMn; k0 += 16) {
        // Load x tile [128 rows x 16 k] -> As[k][row] (transposed)
        #pragma unroll
        for (int i = 0; i < 2; i++) {
            int f  = i * 256 + tid;       // 0..511 float4 index
            int r  = f >> 2;              // 0..127 row
            int kk = (f & 3) << 2;        // 0,4,8,12
            float4 v4 = *(const float4*)(x + (size_t)(row0 + r) * DMn + k0 + kk);
            As[kk + 0][r] = v4.x; As[kk + 1][r] = v4.y;
            As[kk + 2][r] = v4.z; As[kk + 3][r] = v4.w;
        }
        // Load W tile [16 k x 64 n]
        {
            int kr = tid >> 4;
            int nc = (tid & 15) << 2;
            *(float4*)&Bs[kr][nc] = *(const float4*)(W + (size_t)(k0 + kr) * DKn + nc);
        }
        __syncthreads();

        #pragma unroll
        for (int k = 0; k < 16; k++) {
            float4 a0 = *(const float4*)&As[k][ty * 8];
            float4 a1 = *(const float4*)&As[k][ty * 8 + 4];
            float4 b0 = *(const float4*)&Bs[k][tx * 4];
            float a[8] = {a0.x, a0.y, a0.z, a0.w, a1.x, a1.y, a1.z, a1.w};
            float bb[4] = {b0.x, b0.y, b0.z, b0.w};
            #pragma unroll
            for (int i = 0; i < 8; i++)
                #pragma unroll
                for (int j = 0; j < 4; j++)
                    acc[i][j] = fmaf(a[i], bb[j], acc[i][j]);
        }
        __syncthreads();
    }

    // Store to [B,H,S,64]
    #pragma unroll
    for (int i = 0; i < 8; i++) {
        int t = row0 + ty * 8 + i;
        int b = t >> 11;            // S = 2048
        int s = t & (Sn - 1);
        float* op = out + (((size_t)(b * Hn + head) * Sn + s) * DKn) + tx * 4;
        *(float4*)op = make_float4(acc[i][0], acc[i][1], acc[i][2], acc[i][3]);
    }
}

// ============================================================================
// Kernel 2: flash attention. grid = (Sn/128, B*H), block = 128 (1 q-row/thread)
// ============================================================================
__global__ __launch_bounds__(128) void attn_kernel()
{
    __shared__ float Ks[32][64];
    __shared__ float Vs[32][64];
    __shared__ float Ss[128][33];   // per-thread score row (reg-pressure spill), padded

    const int bh  = blockIdx.y;
    const int q0  = blockIdx.x * 128;
    const int tid = threadIdx.x;

    const float* Qp = g_q + (size_t)bh * Sn * DKn;
    const float* Kp = g_k + (size_t)bh * Sn * DKn;
    const float* Vp = g_v + (size_t)bh * Sn * DKn;

    // Load q row, pre-scaled by 1/sqrt(64)
    float q[64];
    {
        const float* qptr = Qp + (size_t)(q0 + tid) * DKn;
        #pragma unroll
        for (int d = 0; d < 64; d += 4) {
            float4 t4 = *(const float4*)(qptr + d);
            q[d + 0] = t4.x * 0.125f; q[d + 1] = t4.y * 0.125f;
            q[d + 2] = t4.z * 0.125f; q[d + 3] = t4.w * 0.125f;
        }
    }

    float o[64];
    #pragma unroll
    for (int d = 0; d < 64; d++) o[d] = 0.f;
    float m = -1e30f, l = 0.f;
    float* srow = &Ss[tid][0];

    for (int kv0 = 0; kv0 < Sn; kv0 += 32) {
        __syncthreads();   // protect Ks/Vs from previous tile's readers
        // Load K,V tiles [32 x 64] (coalesced float4)
        #pragma unroll
        for (int i = 0; i < 4; i++) {
            int f = i * 128 + tid;        // 0..511
            int r = f >> 4;               // 0..31
            int c = (f & 15) << 2;        // 0..60
            *(float4*)&Ks[r][c] = *(const float4*)(Kp + (size_t)(kv0 + r) * DKn + c);
            *(float4*)&Vs[r][c] = *(const float4*)(Vp + (size_t)(kv0 + r) * DKn + c);
        }
        __syncthreads();

        // Dots: 4 kv rows at a time (ILP=4), track tile max
        float tmax = -1e30f;
        #pragma unroll 1
        for (int j0 = 0; j0 < 32; j0 += 4) {
            float s0 = 0.f, s1 = 0.f, s2 = 0.f, s3 = 0.f;
            #pragma unroll
            for (int d = 0; d < 64; d += 4) {
                float4 k0v = *(const float4*)&Ks[j0 + 0][d];
                float4 k1v = *(const float4*)&Ks[j0 + 1][d];
                float4 k2v = *(const float4*)&Ks[j0 + 2][d];
                float4 k3v = *(const float4*)&Ks[j0 + 3][d];
                s0 = fmaf(q[d], k0v.x, s0); s0 = fmaf(q[d+1], k0v.y, s0);
                s0 = fmaf(q[d+2], k0v.z, s0); s0 = fmaf(q[d+3], k0v.w, s0);
                s1 = fmaf(q[d], k1v.x, s1); s1 = fmaf(q[d+1], k1v.y, s1);
                s1 = fmaf(q[d+2], k1v.z, s1); s1 = fmaf(q[d+3], k1v.w, s1);
                s2 = fmaf(q[d], k2v.x, s2); s2 = fmaf(q[d+1], k2v.y, s2);
                s2 = fmaf(q[d+2], k2v.z, s2); s2 = fmaf(q[d+3], k2v.w, s2);
                s3 = fmaf(q[d], k3v.x, s3); s3 = fmaf(q[d+1], k3v.y, s3);
                s3 = fmaf(q[d+2], k3v.z, s3); s3 = fmaf(q[d+3], k3v.w, s3);
            }
            srow[j0 + 0] = s0; srow[j0 + 1] = s1;
            srow[j0 + 2] = s2; srow[j0 + 3] = s3;
            tmax = fmaxf(tmax, fmaxf(fmaxf(s0, s1), fmaxf(s2, s3)));
        }

        // Online softmax rescale
        float mnew = fmaxf(m, tmax);
        float corr = __expf(m - mnew);   // first tile: exp(-huge) = 0
        l *= corr;
        #pragma unroll
        for (int d = 0; d < 64; d++) o[d] *= corr;
        m = mnew;

        // P @ V accumulation
        #pragma unroll 1
        for (int j = 0; j < 32; j++) {
            float p = __expf(srow[j] - mnew);
            l += p;
            #pragma unroll
            for (int d = 0; d < 64; d += 4) {
                float4 v4 = *(const float4*)&Vs[j][d];
                o[d + 0] = fmaf(p, v4.x, o[d + 0]);
                o[d + 1] = fmaf(p, v4.y, o[d + 1]);
                o[d + 2] = fmaf(p, v4.z, o[d + 2]);
                o[d + 3] = fmaf(p, v4.w, o[d + 3]);
            }
        }
    }

    // Write ctx in [B, S, H*64] layout (ready for output GEMM)
    const float inv_l = 1.f / l;
    const int b = bh >> 4;
    const int h = bh & 15;
    const int trow = b * Sn + q0 + tid;
    float* cptr = g_ctx + (size_t)trow * DMn + h * DKn;
    #pragma unroll
    for (int d = 0; d < 64; d += 4) {
        *(float4*)(cptr + d) = make_float4(o[d] * inv_l, o[d + 1] * inv_l,
                                           o[d + 2] * inv_l, o[d + 3] * inv_l);
    }
}

// ============================================================================
// Kernel 3: output projection. out[4096,1024] = ctx[4096,1024] @ Wo[1024,1024]
// grid = (Tn/128, 1024/64), block = 256
// ============================================================================
__global__ __launch_bounds__(256) void outproj_kernel(
    const float* __restrict__ Wo, float* __restrict__ Cout)
{
    __shared__ float As[16][132];
    __shared__ float Bs[16][64];

    const int row0 = blockIdx.x * 128;
    const int n0   = blockIdx.y * 64;
    const int tid  = threadIdx.x;
    const int tx   = tid & 15;
    const int ty   = tid >> 4;

    float acc[8][4];
    #pragma unroll
    for (int i = 0; i < 8; i++) {
        acc[i][0] = 0.f; acc[i][1] = 0.f; acc[i][2] = 0.f; acc[i][3] = 0.f;
    }

    for (int k0 = 0; k0 < DMn; k0 += 16) {
        #pragma unroll
        for (int i = 0; i < 2; i++) {
            int f  = i * 256 + tid;
            int r  = f >> 2;
            int kk = (f & 3) << 2;
            float4 v4 = *(const float4*)(g_ctx + (size_t)(row0 + r) * DMn + k0 + kk);
            As[kk + 0][r] = v4.x; As[kk + 1][r] = v4.y;
            As[kk + 2][r] = v4.z; As[kk + 3][r] = v4.w;
        }
        {
            int kr = tid >> 4;
            int nc = (tid & 15) << 2;
            *(float4*)&Bs[kr][nc] = *(const float4*)(Wo + (size_t)(k0 + kr) * DMn + n0 + nc);
        }
        __syncthreads();

        #pragma unroll
        for (int k = 0; k < 16; k++) {
            float4 a0 = *(const float4*)&As[k][ty * 8];
            float4 a1 = *(const float4*)&As[k][ty * 8 + 4];
            float4 b0 = *(const float4*)&Bs[k][tx * 4];
            float a[8] = {a0.x, a0.y, a0.z, a0.w, a1.x, a1.y, a1.z, a1.w};
            float bb[4] = {b0.x, b0.y, b0.z, b0.w};
            #pragma unroll
            for (int i = 0; i < 8; i++)
                #pragma unroll
                for (int j = 0; j < 4; j++)
                    acc[i][j] = fmaf(a[i], bb[j], acc[i][j]);
        }
        __syncthreads();
    }

    #pragma unroll
    for (int i = 0; i < 8; i++) {
        int t = row0 + ty * 8 + i;
        float* op = Cout + (size_t)t * DMn + n0 + tx * 4;
        *(float4*)op = make_float4(acc[i][0], acc[i][1], acc[i][2], acc[i][3]);
    }
}

// ============================================================================
// Launch. Input order per metadata / reference dict: x, Wk, Wq, Wv, Wo
// ============================================================================
extern "C" void kernel_launch(void* const* d_in, const int* in_sizes, int n_in,
                              void* d_out, int out_size)
{
    const float* x  = (const float*)d_in[0];
    const float* Wk = (const float*)d_in[1];
    const float* Wq = (const float*)d_in[2];
    const float* Wv = (const float*)d_in[3];
    const float* Wo = (const float*)d_in[4];
    float* out = (float*)d_out;
    (void)in_sizes; (void)n_in; (void)out_size;

    qkv_kernel<<<dim3(Tn / 128, 48), 256>>>(x, Wq, Wk, Wv);
    attn_kernel<<<dim3(Sn / 128, Bn * Hn), 128>>>();
    outproj_kernel<<<dim3(Tn / 128, DMn / 64), 256>>>(Wo, out);
}